// round 2
// baseline (speedup 1.0000x reference)
#include <cuda_runtime.h>
#include <cuda_bf16.h>
#include <mma.h>
#include <cstdint>
#include <cstddef>

using namespace nvcuda;

#define NN    10000
#define NPAD  10112          // 79 * 128
#define CDIM  2112           // 66 * 32
#define BATCH 32
#define HID   64
#define DFE   66

// ---------------- scratch (__device__ globals; zero-initialized) ----------------
__device__ __nv_bfloat16 g_Abf[(size_t)NN * NN];          // 200 MB
__device__ float         g_x0 [(size_t)NPAD * CDIM];      // fp32 x0 (current gconv)
__device__ float         g_x1 [(size_t)NPAD * CDIM];
__device__ float         g_x2 [(size_t)NPAD * CDIM];
__device__ __nv_bfloat16 g_Xa [(size_t)NPAD * CDIM];      // bf16 GEMM input (x0)
__device__ __nv_bfloat16 g_Xb [(size_t)NPAD * CDIM];      // bf16 GEMM input (x1)
__device__ float         g_u  [(size_t)BATCH * NN * HID];
__device__ float         g_rs [(size_t)BATCH * NN * HID]; // r * states

// ---------------- helpers ----------------
__device__ __forceinline__ void cp16(void* dst, const void* src, bool pred) {
    uint32_t d = (uint32_t)__cvta_generic_to_shared(dst);
    int sz = pred ? 16 : 0;
    asm volatile("cp.async.cg.shared.global [%0], [%1], 16, %2;\n"
                 :: "r"(d), "l"(src), "r"(sz));
}
__device__ __forceinline__ void cp_commit() { asm volatile("cp.async.commit_group;\n"); }
__device__ __forceinline__ void cp_wait1()  { asm volatile("cp.async.wait_group 1;\n"); }

__device__ __forceinline__ float sigf(float x) { return 1.f / (1.f + __expf(-x)); }

// ---------------- K1: A fp32 -> bf16 ----------------
__global__ void conv_A(const float* __restrict__ A) {
    size_t i      = (size_t)blockIdx.x * blockDim.x + threadIdx.x;
    size_t stride = (size_t)gridDim.x * blockDim.x;
    size_t total  = (size_t)NN * NN / 4;
    for (size_t v = i; v < total; v += stride) {
        float4 f = ((const float4*)A)[v];
        ((__nv_bfloat162*)g_Abf)[v*2  ] = __floats2bfloat162_rn(f.x, f.y);
        ((__nv_bfloat162*)g_Abf)[v*2+1] = __floats2bfloat162_rn(f.z, f.w);
    }
}

// ---------------- K2: build x0 = concat(inputs, states), layout [n, d*32+b] ----------------
__global__ void build_x0_k(const float* __restrict__ inputs, const float* __restrict__ states) {
    int n = blockIdx.x, tid = threadIdx.x;
    __shared__ float s[64][33];
    for (int i = tid; i < BATCH * HID; i += 256) {
        int b = i >> 6, h = i & 63;
        s[h][b] = states[((size_t)b * NN + n) * HID + h];
    }
    __syncthreads();
    size_t row = (size_t)n * CDIM;
    for (int c = tid; c < CDIM; c += 256) {
        int d = c >> 5, b = c & 31;
        float v = (d < 2) ? inputs[((size_t)b * NN + n) * 2 + d] : s[d - 2][b];
        g_x0[row + c] = v;
        g_Xa[row + c] = __float2bfloat16(v);
    }
}

// ---------------- K6: x0 state-columns <- r*states ----------------
__global__ void update_x0_k() {
    int n = blockIdx.x, tid = threadIdx.x;
    __shared__ float s[64][33];
    for (int i = tid; i < BATCH * HID; i += 256) {
        int b = i >> 6, h = i & 63;
        s[h][b] = g_rs[((size_t)b * NN + n) * HID + h];
    }
    __syncthreads();
    size_t row = (size_t)n * CDIM;
    for (int c = 64 + tid; c < CDIM; c += 256) {
        int d = c >> 5, b = c & 31;
        float v = s[d - 2][b];
        g_x0[row + c] = v;
        g_Xa[row + c] = __float2bfloat16(v);
    }
}

// ---------------- GEMM: out = A @ X   (bf16 x bf16 -> fp32) ----------------
// MODE 0: X=g_Xa, write fp32->g_x1 and bf16->g_Xb
// MODE 1: X=g_Xb, write fp32 (2*acc - g_x0) -> g_x2
template <int MODE>
__global__ __launch_bounds__(256) void gemm_kernel() {
    const __nv_bfloat16* __restrict__ A = g_Abf;
    const __nv_bfloat16* __restrict__ X = (MODE == 0) ? g_Xa : g_Xb;

    __shared__ alignas(16) char shraw[36864];
    __nv_bfloat16* As = (__nv_bfloat16*)shraw;             // [2][128][24]
    __nv_bfloat16* Bs = (__nv_bfloat16*)(shraw + 12288);   // [2][16][72]
    float*         Cs = (float*)shraw;                     // [128][72]
#define AS_(s,r,c) As[(s)*3072 + (r)*24 + (c)]
#define BS_(s,r,c) Bs[(s)*1152 + (r)*72 + (c)]

    const int tid  = threadIdx.x;
    const int bm   = blockIdx.y, bn = blockIdx.x;
    const int warp = tid >> 5;
    const int wr   = warp & 3, wc = warp >> 2;   // 4x2 warp grid -> 32x32 per warp

    wmma::fragment<wmma::accumulator, 16, 16, 16, float> acc[2][2];
#pragma unroll
    for (int i = 0; i < 2; ++i)
#pragma unroll
        for (int j = 0; j < 2; ++j) wmma::fill_fragment(acc[i][j], 0.0f);

    // A tile loaders: 256 threads x 16B = 128 rows x 32B
    const int  arow  = tid >> 1, ahalf = tid & 1;
    const int  garow = bm * 128 + arow;
    const bool aval  = garow < NN;
    const __nv_bfloat16* asrc = A + (size_t)(aval ? garow : 0) * NN + ahalf * 8;
    // B tile loaders: 128 threads x 16B = 16 rows x 128B
    const int  brow = tid >> 3, bc8 = tid & 7;
    const __nv_bfloat16* bsrc = X + (size_t)brow * CDIM + (size_t)bn * 64 + bc8 * 8;

    cp16(&AS_(0, arow, ahalf * 8), asrc, aval);
    if (tid < 128) cp16(&BS_(0, brow, bc8 * 8), bsrc, true);
    cp_commit();

    const int KT = NN / 16;   // 625
    for (int k = 0; k < KT; ++k) {
        int s = k & 1;
        if (k + 1 < KT) {
            int ns = s ^ 1;
            cp16(&AS_(ns, arow, ahalf * 8), asrc + (size_t)(k + 1) * 16, aval);
            if (tid < 128) cp16(&BS_(ns, brow, bc8 * 8), bsrc + (size_t)(k + 1) * 16 * CDIM, true);
        }
        cp_commit();
        cp_wait1();
        __syncthreads();

        wmma::fragment<wmma::matrix_a, 16, 16, 16, __nv_bfloat16, wmma::row_major> af;
        wmma::fragment<wmma::matrix_b, 16, 16, 16, __nv_bfloat16, wmma::row_major> bfr[2];
        wmma::load_matrix_sync(bfr[0], &BS_(s, 0, wc * 32     ), 72);
        wmma::load_matrix_sync(bfr[1], &BS_(s, 0, wc * 32 + 16), 72);
#pragma unroll
        for (int i = 0; i < 2; ++i) {
            wmma::load_matrix_sync(af, &AS_(s, wr * 32 + i * 16, 0), 24);
            wmma::mma_sync(acc[i][0], af, bfr[0], acc[i][0]);
            wmma::mma_sync(acc[i][1], af, bfr[1], acc[i][1]);
        }
        __syncthreads();
    }

    // epilogue: stage through smem, then fused math + global stores (padded rows, no guards)
#pragma unroll
    for (int i = 0; i < 2; ++i)
#pragma unroll
        for (int j = 0; j < 2; ++j)
            wmma::store_matrix_sync(&Cs[(wr * 32 + i * 16) * 72 + wc * 32 + j * 16],
                                    acc[i][j], 72, wmma::mem_row_major);
    __syncthreads();

    for (int i = tid; i < 128 * 16; i += 256) {
        int r = i >> 4, c4 = i & 15;
        float4 v = *(float4*)&Cs[r * 72 + c4 * 4];
        size_t off = (size_t)(bm * 128 + r) * CDIM + (size_t)bn * 64 + c4 * 4;
        if (MODE == 0) {
            *(float4*)(g_x1 + off) = v;
            *(__nv_bfloat162*)(g_Xb + off    ) = __floats2bfloat162_rn(v.x, v.y);
            *(__nv_bfloat162*)(g_Xb + off + 2) = __floats2bfloat162_rn(v.z, v.w);
        } else {
            float4 x = *(const float4*)(g_x0 + off);
            v.x = 2.f * v.x - x.x; v.y = 2.f * v.y - x.y;
            v.z = 2.f * v.z - x.z; v.w = 2.f * v.w - x.w;
            *(float4*)(g_x2 + off) = v;
        }
    }
#undef AS_
#undef BS_
}

// ---------------- K5: ru = sigmoid(xk @ Wru + bru); emit u and r*states ----------------
__global__ __launch_bounds__(256) void ru_kernel(const float* __restrict__ Wru,
                                                 const float* __restrict__ bru,
                                                 const float* __restrict__ states) {
    int n = blockIdx.x, tid = threadIdx.x;
    __shared__ float xr[3][CDIM];
    {
        const float4* p0 = (const float4*)(g_x0 + (size_t)n * CDIM);
        const float4* p1 = (const float4*)(g_x1 + (size_t)n * CDIM);
        const float4* p2 = (const float4*)(g_x2 + (size_t)n * CDIM);
        for (int i = tid; i < CDIM / 4; i += 256) {
            ((float4*)xr[0])[i] = p0[i];
            ((float4*)xr[1])[i] = p1[i];
            ((float4*)xr[2])[i] = p2[i];
        }
    }
    __syncthreads();

    const int hq = tid & 31, bg = tid >> 5;   // h0 = hq*4 in [0,128), b = bg + 8j
    const int h0 = hq * 4;
    float4 acc[4];
    float4 bb = *(const float4*)&bru[h0];
#pragma unroll
    for (int j = 0; j < 4; ++j) acc[j] = bb;

    for (int d = 0; d < DFE; ++d) {
        float4 w0 = *(const float4*)&Wru[(d * 3 + 0) * 128 + h0];
        float4 w1 = *(const float4*)&Wru[(d * 3 + 1) * 128 + h0];
        float4 w2 = *(const float4*)&Wru[(d * 3 + 2) * 128 + h0];
#pragma unroll
        for (int j = 0; j < 4; ++j) {
            int b = bg + 8 * j;
            float x0v = xr[0][d * 32 + b];
            float x1v = xr[1][d * 32 + b];
            float x2v = xr[2][d * 32 + b];
            acc[j].x += x0v * w0.x + x1v * w1.x + x2v * w2.x;
            acc[j].y += x0v * w0.y + x1v * w1.y + x2v * w2.y;
            acc[j].z += x0v * w0.z + x1v * w1.z + x2v * w2.z;
            acc[j].w += x0v * w0.w + x1v * w1.w + x2v * w2.w;
        }
    }

#pragma unroll
    for (int j = 0; j < 4; ++j) {
        int b = bg + 8 * j;
        size_t base = ((size_t)b * NN + n) * HID;
        float4 s4;
        s4.x = sigf(acc[j].x); s4.y = sigf(acc[j].y);
        s4.z = sigf(acc[j].z); s4.w = sigf(acc[j].w);
        if (h0 < 64) {  // r half
            float4 sv = *(const float4*)&states[base + h0];
            float4 rs;
            rs.x = s4.x * sv.x; rs.y = s4.y * sv.y;
            rs.z = s4.z * sv.z; rs.w = s4.w * sv.w;
            *(float4*)&g_rs[base + h0] = rs;
        } else {        // u half
            *(float4*)&g_u[base + h0 - 64] = s4;
        }
    }
}

// ---------------- K9: c = tanh(xk @ Wc + bc); out = u*s + (1-u)*c ----------------
__global__ __launch_bounds__(256) void out_kernel(const float* __restrict__ Wc,
                                                  const float* __restrict__ bc,
                                                  const float* __restrict__ states,
                                                  float* __restrict__ out) {
    int n = blockIdx.x, tid = threadIdx.x;
    __shared__ float xr[3][CDIM];
    {
        const float4* p0 = (const float4*)(g_x0 + (size_t)n * CDIM);
        const float4* p1 = (const float4*)(g_x1 + (size_t)n * CDIM);
        const float4* p2 = (const float4*)(g_x2 + (size_t)n * CDIM);
        for (int i = tid; i < CDIM / 4; i += 256) {
            ((float4*)xr[0])[i] = p0[i];
            ((float4*)xr[1])[i] = p1[i];
            ((float4*)xr[2])[i] = p2[i];
        }
    }
    __syncthreads();

    const int hq = tid & 15, bg = tid >> 4;   // h0 = hq*4 in [0,64), b = bg + 16j
    const int h0 = hq * 4;
    float4 acc[2];
    float4 bb = *(const float4*)&bc[h0];
    acc[0] = bb; acc[1] = bb;

    for (int d = 0; d < DFE; ++d) {
        float4 w0 = *(const float4*)&Wc[(d * 3 + 0) * 64 + h0];
        float4 w1 = *(const float4*)&Wc[(d * 3 + 1) * 64 + h0];
        float4 w2 = *(const float4*)&Wc[(d * 3 + 2) * 64 + h0];
#pragma unroll
        for (int j = 0; j < 2; ++j) {
            int b = bg + 16 * j;
            float x0v = xr[0][d * 32 + b];
            float x1v = xr[1][d * 32 + b];
            float x2v = xr[2][d * 32 + b];
            acc[j].x += x0v * w0.x + x1v * w1.x + x2v * w2.x;
            acc[j].y += x0v * w0.y + x1v * w1.y + x2v * w2.y;
            acc[j].z += x0v * w0.z + x1v * w1.z + x2v * w2.z;
            acc[j].w += x0v * w0.w + x1v * w1.w + x2v * w2.w;
        }
    }

#pragma unroll
    for (int j = 0; j < 2; ++j) {
        int b = bg + 16 * j;
        size_t base = ((size_t)b * NN + n) * HID + h0;
        float4 u4 = *(const float4*)&g_u[base];
        float4 sv = *(const float4*)&states[base];
        float4 o;
        float c0 = tanhf(acc[j].x), c1 = tanhf(acc[j].y),
              c2 = tanhf(acc[j].z), c3 = tanhf(acc[j].w);
        o.x = u4.x * sv.x + (1.f - u4.x) * c0;
        o.y = u4.y * sv.y + (1.f - u4.y) * c1;
        o.z = u4.z * sv.z + (1.f - u4.z) * c2;
        o.w = u4.w * sv.w + (1.f - u4.w) * c3;
        *(float4*)&out[base] = o;
    }
}

// ---------------- launcher ----------------
extern "C" void kernel_launch(void* const* d_in, const int* in_sizes, int n_in,
                              void* d_out, int out_size) {
    const float *inputs = nullptr, *states = nullptr, *A = nullptr;
    const float *Wru = nullptr, *bru = nullptr, *Wc = nullptr, *bc = nullptr;
    for (int i = 0; i < n_in; ++i) {
        const float* p = (const float*)d_in[i];
        switch (in_sizes[i]) {
            case 640000:    inputs = p; break;
            case 20480000:  states = p; break;
            case 100000000: A      = p; break;
            case 25344:     Wru    = p; break;
            case 128:       bru    = p; break;
            case 12672:     Wc     = p; break;
            case 64:        bc     = p; break;
            default: break;
        }
    }
    float* out = (float*)d_out;

    conv_A<<<2048, 256>>>(A);
    build_x0_k<<<NN, 256>>>(inputs, states);

    dim3 g(CDIM / 64, NPAD / 128);   // 33 x 79
    gemm_kernel<0><<<g, 256>>>();    // x1 = A @ x0
    gemm_kernel<1><<<g, 256>>>();    // x2 = 2*A@x1 - x0
    ru_kernel<<<NN, 256>>>(Wru, bru, states);
    update_x0_k<<<NN, 256>>>();
    gemm_kernel<0><<<g, 256>>>();    // x1' = A @ x0'
    gemm_kernel<1><<<g, 256>>>();    // x2' = 2*A@x1' - x0'
    out_kernel<<<NN, 256>>>(Wc, bc, states, out);
}

// round 3
// speedup vs baseline: 1.5354x; 1.5354x over previous
#include <cuda_runtime.h>
#include <cuda_bf16.h>
#include <mma.h>
#include <cstdint>
#include <cstddef>

using namespace nvcuda;

#define NN    10000
#define NPAD  10112          // 79 * 128
#define CDIM  2112           // 66 * 32
#define BATCH 32
#define HID   64
#define DFE   66

// ---------------- scratch (__device__ globals; zero-initialized) ----------------
__device__ __nv_bfloat16 g_Abf[(size_t)NN * NN];          // 200 MB
__device__ float         g_x0 [(size_t)NPAD * CDIM];      // fp32 x0 (current gconv)
__device__ float         g_x1 [(size_t)NPAD * CDIM];
__device__ float         g_x2 [(size_t)NPAD * CDIM];
__device__ __nv_bfloat16 g_Xa [(size_t)NPAD * CDIM];      // bf16 GEMM input (x0)
__device__ __nv_bfloat16 g_Xb [(size_t)NPAD * CDIM];      // bf16 GEMM input (x1)
__device__ float         g_u  [(size_t)BATCH * NN * HID];
__device__ float         g_rs [(size_t)BATCH * NN * HID]; // r * states

// ---------------- helpers ----------------
__device__ __forceinline__ void cp16(void* dst, const void* src, bool pred) {
    uint32_t d = (uint32_t)__cvta_generic_to_shared(dst);
    int sz = pred ? 16 : 0;
    asm volatile("cp.async.cg.shared.global [%0], [%1], 16, %2;\n"
                 :: "r"(d), "l"(src), "r"(sz));
}
__device__ __forceinline__ void cp_commit() { asm volatile("cp.async.commit_group;\n"); }
__device__ __forceinline__ void cp_wait1()  { asm volatile("cp.async.wait_group 1;\n"); }

__device__ __forceinline__ float sigf(float x) { return 1.f / (1.f + __expf(-x)); }

// ---------------- K1: A fp32 -> bf16 ----------------
__global__ void conv_A(const float* __restrict__ A) {
    size_t i      = (size_t)blockIdx.x * blockDim.x + threadIdx.x;
    size_t stride = (size_t)gridDim.x * blockDim.x;
    size_t total  = (size_t)NN * NN / 4;
    for (size_t v = i; v < total; v += stride) {
        float4 f = ((const float4*)A)[v];
        ((__nv_bfloat162*)g_Abf)[v*2  ] = __floats2bfloat162_rn(f.x, f.y);
        ((__nv_bfloat162*)g_Abf)[v*2+1] = __floats2bfloat162_rn(f.z, f.w);
    }
}

// ---------------- K2: build x0 = concat(inputs, states), layout [n, d*32+b] ----------------
__global__ void build_x0_k(const float* __restrict__ inputs, const float* __restrict__ states) {
    int n = blockIdx.x, tid = threadIdx.x;
    __shared__ float s[64][33];
    for (int i = tid; i < BATCH * HID; i += 256) {
        int b = i >> 6, h = i & 63;
        s[h][b] = states[((size_t)b * NN + n) * HID + h];
    }
    __syncthreads();
    size_t row = (size_t)n * CDIM;
    for (int c = tid; c < CDIM; c += 256) {
        int d = c >> 5, b = c & 31;
        float v = (d < 2) ? inputs[((size_t)b * NN + n) * 2 + d] : s[d - 2][b];
        g_x0[row + c] = v;
        g_Xa[row + c] = __float2bfloat16(v);
    }
}

// ---------------- K6: x0 state-columns <- r*states ----------------
__global__ void update_x0_k() {
    int n = blockIdx.x, tid = threadIdx.x;
    __shared__ float s[64][33];
    for (int i = tid; i < BATCH * HID; i += 256) {
        int b = i >> 6, h = i & 63;
        s[h][b] = g_rs[((size_t)b * NN + n) * HID + h];
    }
    __syncthreads();
    size_t row = (size_t)n * CDIM;
    for (int c = 64 + tid; c < CDIM; c += 256) {
        int d = c >> 5, b = c & 31;
        float v = s[d - 2][b];
        g_x0[row + c] = v;
        g_Xa[row + c] = __float2bfloat16(v);
    }
}

// ---------------- GEMM: out = A @ X   (bf16 x bf16 -> fp32) ----------------
// MODE 0: X=g_Xa, write fp32->g_x1 and bf16->g_Xb
// MODE 1: X=g_Xb, write fp32 (2*acc - g_x0) -> g_x2
template <int MODE>
__global__ __launch_bounds__(256) void gemm_kernel() {
    const __nv_bfloat16* __restrict__ A = g_Abf;
    const __nv_bfloat16* __restrict__ X = (MODE == 0) ? g_Xa : g_Xb;

    __shared__ alignas(16) char shraw[36864];
    __nv_bfloat16* As = (__nv_bfloat16*)shraw;             // [2][128][24]
    __nv_bfloat16* Bs = (__nv_bfloat16*)(shraw + 12288);   // [2][16][72]
    float*         Cs = (float*)shraw;                     // [128][72]
#define AS_(s,r,c) As[(s)*3072 + (r)*24 + (c)]
#define BS_(s,r,c) Bs[(s)*1152 + (r)*72 + (c)]

    const int tid  = threadIdx.x;
    const int bm   = blockIdx.y, bn = blockIdx.x;
    const int warp = tid >> 5;
    const int wr   = warp & 3, wc = warp >> 2;   // 4x2 warp grid -> 32x32 per warp

    wmma::fragment<wmma::accumulator, 16, 16, 16, float> acc[2][2];
#pragma unroll
    for (int i = 0; i < 2; ++i)
#pragma unroll
        for (int j = 0; j < 2; ++j) wmma::fill_fragment(acc[i][j], 0.0f);

    // A tile loaders: 256 threads x 16B = 128 rows x 32B
    const int  arow  = tid >> 1, ahalf = tid & 1;
    const int  garow = bm * 128 + arow;
    const bool aval  = garow < NN;
    const __nv_bfloat16* asrc = A + (size_t)(aval ? garow : 0) * NN + ahalf * 8;
    // B tile loaders: 128 threads x 16B = 16 rows x 128B
    const int  brow = tid >> 3, bc8 = tid & 7;
    const __nv_bfloat16* bsrc = X + (size_t)brow * CDIM + (size_t)bn * 64 + bc8 * 8;

    cp16(&AS_(0, arow, ahalf * 8), asrc, aval);
    if (tid < 128) cp16(&BS_(0, brow, bc8 * 8), bsrc, true);
    cp_commit();

    const int KT = NN / 16;   // 625
    for (int k = 0; k < KT; ++k) {
        int s = k & 1;
        if (k + 1 < KT) {
            int ns = s ^ 1;
            cp16(&AS_(ns, arow, ahalf * 8), asrc + (size_t)(k + 1) * 16, aval);
            if (tid < 128) cp16(&BS_(ns, brow, bc8 * 8), bsrc + (size_t)(k + 1) * 16 * CDIM, true);
        }
        cp_commit();
        cp_wait1();
        __syncthreads();

        wmma::fragment<wmma::matrix_a, 16, 16, 16, __nv_bfloat16, wmma::row_major> af;
        wmma::fragment<wmma::matrix_b, 16, 16, 16, __nv_bfloat16, wmma::row_major> bfr[2];
        wmma::load_matrix_sync(bfr[0], &BS_(s, 0, wc * 32     ), 72);
        wmma::load_matrix_sync(bfr[1], &BS_(s, 0, wc * 32 + 16), 72);
#pragma unroll
        for (int i = 0; i < 2; ++i) {
            wmma::load_matrix_sync(af, &AS_(s, wr * 32 + i * 16, 0), 24);
            wmma::mma_sync(acc[i][0], af, bfr[0], acc[i][0]);
            wmma::mma_sync(acc[i][1], af, bfr[1], acc[i][1]);
        }
        __syncthreads();
    }

    // epilogue: stage through smem, then fused math + global stores (padded rows, no guards)
#pragma unroll
    for (int i = 0; i < 2; ++i)
#pragma unroll
        for (int j = 0; j < 2; ++j)
            wmma::store_matrix_sync(&Cs[(wr * 32 + i * 16) * 72 + wc * 32 + j * 16],
                                    acc[i][j], 72, wmma::mem_row_major);
    __syncthreads();

    for (int i = tid; i < 128 * 16; i += 256) {
        int r = i >> 4, c4 = i & 15;
        float4 v = *(float4*)&Cs[r * 72 + c4 * 4];
        size_t off = (size_t)(bm * 128 + r) * CDIM + (size_t)bn * 64 + c4 * 4;
        if (MODE == 0) {
            *(float4*)(g_x1 + off) = v;
            *(__nv_bfloat162*)(g_Xb + off    ) = __floats2bfloat162_rn(v.x, v.y);
            *(__nv_bfloat162*)(g_Xb + off + 2) = __floats2bfloat162_rn(v.z, v.w);
        } else {
            float4 x = *(const float4*)(g_x0 + off);
            v.x = 2.f * v.x - x.x; v.y = 2.f * v.y - x.y;
            v.z = 2.f * v.z - x.z; v.w = 2.f * v.w - x.w;
            *(float4*)(g_x2 + off) = v;
        }
    }
#undef AS_
#undef BS_
}

// ---------------- K5: ru = sigmoid(xk @ Wru + bru); emit u and r*states ----------------
__global__ __launch_bounds__(256) void ru_kernel(const float* __restrict__ Wru,
                                                 const float* __restrict__ bru,
                                                 const float* __restrict__ states) {
    int n = blockIdx.x, tid = threadIdx.x;
    __shared__ float xr[3][CDIM];
    {
        const float4* p0 = (const float4*)(g_x0 + (size_t)n * CDIM);
        const float4* p1 = (const float4*)(g_x1 + (size_t)n * CDIM);
        const float4* p2 = (const float4*)(g_x2 + (size_t)n * CDIM);
        for (int i = tid; i < CDIM / 4; i += 256) {
            ((float4*)xr[0])[i] = p0[i];
            ((float4*)xr[1])[i] = p1[i];
            ((float4*)xr[2])[i] = p2[i];
        }
    }
    __syncthreads();

    const int hq = tid & 31, bg = tid >> 5;   // h0 = hq*4 in [0,128), b = bg + 8j
    const int h0 = hq * 4;
    float4 acc[4];
    float4 bb = *(const float4*)&bru[h0];
#pragma unroll
    for (int j = 0; j < 4; ++j) acc[j] = bb;

    for (int d = 0; d < DFE; ++d) {
        float4 w0 = *(const float4*)&Wru[(d * 3 + 0) * 128 + h0];
        float4 w1 = *(const float4*)&Wru[(d * 3 + 1) * 128 + h0];
        float4 w2 = *(const float4*)&Wru[(d * 3 + 2) * 128 + h0];
#pragma unroll
        for (int j = 0; j < 4; ++j) {
            int b = bg + 8 * j;
            float x0v = xr[0][d * 32 + b];
            float x1v = xr[1][d * 32 + b];
            float x2v = xr[2][d * 32 + b];
            acc[j].x += x0v * w0.x + x1v * w1.x + x2v * w2.x;
            acc[j].y += x0v * w0.y + x1v * w1.y + x2v * w2.y;
            acc[j].z += x0v * w0.z + x1v * w1.z + x2v * w2.z;
            acc[j].w += x0v * w0.w + x1v * w1.w + x2v * w2.w;
        }
    }

#pragma unroll
    for (int j = 0; j < 4; ++j) {
        int b = bg + 8 * j;
        size_t base = ((size_t)b * NN + n) * HID;
        float4 s4;
        s4.x = sigf(acc[j].x); s4.y = sigf(acc[j].y);
        s4.z = sigf(acc[j].z); s4.w = sigf(acc[j].w);
        if (h0 < 64) {  // r half
            float4 sv = *(const float4*)&states[base + h0];
            float4 rs;
            rs.x = s4.x * sv.x; rs.y = s4.y * sv.y;
            rs.z = s4.z * sv.z; rs.w = s4.w * sv.w;
            *(float4*)&g_rs[base + h0] = rs;
        } else {        // u half
            *(float4*)&g_u[base + h0 - 64] = s4;
        }
    }
}

// ---------------- K9: c = tanh(xk @ Wc + bc); out = u*s + (1-u)*c ----------------
__global__ __launch_bounds__(256) void out_kernel(const float* __restrict__ Wc,
                                                  const float* __restrict__ bc,
                                                  const float* __restrict__ states,
                                                  float* __restrict__ out) {
    int n = blockIdx.x, tid = threadIdx.x;
    __shared__ float xr[3][CDIM];
    {
        const float4* p0 = (const float4*)(g_x0 + (size_t)n * CDIM);
        const float4* p1 = (const float4*)(g_x1 + (size_t)n * CDIM);
        const float4* p2 = (const float4*)(g_x2 + (size_t)n * CDIM);
        for (int i = tid; i < CDIM / 4; i += 256) {
            ((float4*)xr[0])[i] = p0[i];
            ((float4*)xr[1])[i] = p1[i];
            ((float4*)xr[2])[i] = p2[i];
        }
    }
    __syncthreads();

    const int hq = tid & 15, bg = tid >> 4;   // h0 = hq*4 in [0,64), b = bg + 16j
    const int h0 = hq * 4;
    float4 acc[2];
    float4 bb = *(const float4*)&bc[h0];
    acc[0] = bb; acc[1] = bb;

    for (int d = 0; d < DFE; ++d) {
        float4 w0 = *(const float4*)&Wc[(d * 3 + 0) * 64 + h0];
        float4 w1 = *(const float4*)&Wc[(d * 3 + 1) * 64 + h0];
        float4 w2 = *(const float4*)&Wc[(d * 3 + 2) * 64 + h0];
#pragma unroll
        for (int j = 0; j < 2; ++j) {
            int b = bg + 16 * j;
            float x0v = xr[0][d * 32 + b];
            float x1v = xr[1][d * 32 + b];
            float x2v = xr[2][d * 32 + b];
            acc[j].x += x0v * w0.x + x1v * w1.x + x2v * w2.x;
            acc[j].y += x0v * w0.y + x1v * w1.y + x2v * w2.y;
            acc[j].z += x0v * w0.z + x1v * w1.z + x2v * w2.z;
            acc[j].w += x0v * w0.w + x1v * w1.w + x2v * w2.w;
        }
    }

#pragma unroll
    for (int j = 0; j < 2; ++j) {
        int b = bg + 16 * j;
        size_t base = ((size_t)b * NN + n) * HID + h0;
        float4 u4 = *(const float4*)&g_u[base];
        float4 sv = *(const float4*)&states[base];
        float4 o;
        float c0 = tanhf(acc[j].x), c1 = tanhf(acc[j].y),
              c2 = tanhf(acc[j].z), c3 = tanhf(acc[j].w);
        o.x = u4.x * sv.x + (1.f - u4.x) * c0;
        o.y = u4.y * sv.y + (1.f - u4.y) * c1;
        o.z = u4.z * sv.z + (1.f - u4.z) * c2;
        o.w = u4.w * sv.w + (1.f - u4.w) * c3;
        *(float4*)&out[base] = o;
    }
}

// ---------------- launcher ----------------
extern "C" void kernel_launch(void* const* d_in, const int* in_sizes, int n_in,
                              void* d_out, int out_size) {
    const float *inputs = nullptr, *states = nullptr, *A = nullptr;
    const float *Wru = nullptr, *bru = nullptr, *Wc = nullptr, *bc = nullptr;
    for (int i = 0; i < n_in; ++i) {
        const float* p = (const float*)d_in[i];
        switch (in_sizes[i]) {
            case 640000:    inputs = p; break;
            case 20480000:  states = p; break;
            case 100000000: A      = p; break;
            case 25344:     Wru    = p; break;
            case 128:       bru    = p; break;
            case 12672:     Wc     = p; break;
            case 64:        bc     = p; break;
            default: break;
        }
    }
    float* out = (float*)d_out;

    conv_A<<<2048, 256>>>(A);
    build_x0_k<<<NN, 256>>>(inputs, states);

    dim3 g(CDIM / 64, NPAD / 128);   // 33 x 79
    gemm_kernel<0><<<g, 256>>>();    // x1 = A @ x0
    gemm_kernel<1><<<g, 256>>>();    // x2 = 2*A@x1 - x0
    ru_kernel<<<NN, 256>>>(Wru, bru, states);
    update_x0_k<<<NN, 256>>>();
    gemm_kernel<0><<<g, 256>>>();    // x1' = A @ x0'
    gemm_kernel<1><<<g, 256>>>();    // x2' = 2*A@x1' - x0'
    out_kernel<<<NN, 256>>>(Wc, bc, states, out);
}

// round 5
// speedup vs baseline: 1.5355x; 1.0001x over previous
#include <cuda_runtime.h>
#include <cuda_bf16.h>
#include <mma.h>
#include <cstdint>
#include <cstddef>

using namespace nvcuda;

#define NN    10000
#define NPAD  10112          // 79 * 128
#define CDIM  2112           // 66 * 32
#define BATCH 32
#define HID   64
#define DFE   66

// ---------------- scratch (__device__ globals; zero-initialized) ----------------
__device__ __nv_bfloat16 g_Abf[(size_t)NN * NN];          // 200 MB
__device__ float         g_x0 [(size_t)NPAD * CDIM];      // fp32 x0 (current gconv)
__device__ float         g_x1 [(size_t)NPAD * CDIM];
__device__ float         g_x2 [(size_t)NPAD * CDIM];
__device__ __nv_bfloat16 g_Xa [(size_t)NPAD * CDIM];      // bf16 GEMM input (x0)
__device__ __nv_bfloat16 g_Xb [(size_t)NPAD * CDIM];      // bf16 GEMM input (x1)
__device__ float         g_u  [(size_t)BATCH * NN * HID];
__device__ float         g_rs [(size_t)BATCH * NN * HID]; // r * states

// ---------------- helpers ----------------
__device__ __forceinline__ void cp16(void* dst, const void* src, bool pred) {
    uint32_t d = (uint32_t)__cvta_generic_to_shared(dst);
    int sz = pred ? 16 : 0;
    asm volatile("cp.async.cg.shared.global [%0], [%1], 16, %2;\n"
                 :: "r"(d), "l"(src), "r"(sz));
}
__device__ __forceinline__ void cp_commit() { asm volatile("cp.async.commit_group;\n"); }
__device__ __forceinline__ void cp_wait1()  { asm volatile("cp.async.wait_group 1;\n"); }

__device__ __forceinline__ float sigf(float x) { return 1.f / (1.f + __expf(-x)); }

// ---------------- K1: A fp32 -> bf16 ----------------
__global__ void conv_A(const float* __restrict__ A) {
    size_t i      = (size_t)blockIdx.x * blockDim.x + threadIdx.x;
    size_t stride = (size_t)gridDim.x * blockDim.x;
    size_t total  = (size_t)NN * NN / 4;
    for (size_t v = i; v < total; v += stride) {
        float4 f = ((const float4*)A)[v];
        ((__nv_bfloat162*)g_Abf)[v*2  ] = __floats2bfloat162_rn(f.x, f.y);
        ((__nv_bfloat162*)g_Abf)[v*2+1] = __floats2bfloat162_rn(f.z, f.w);
    }
}

// ---------------- K2: build x0 = concat(inputs, states), layout [n, d*32+b] ----------------
__global__ void build_x0_k(const float* __restrict__ inputs, const float* __restrict__ states) {
    int n = blockIdx.x, tid = threadIdx.x;
    __shared__ float s[64][33];
    for (int i = tid; i < BATCH * HID; i += 256) {
        int b = i >> 6, h = i & 63;
        s[h][b] = states[((size_t)b * NN + n) * HID + h];
    }
    __syncthreads();
    size_t row = (size_t)n * CDIM;
    for (int c = tid; c < CDIM; c += 256) {
        int d = c >> 5, b = c & 31;
        float v = (d < 2) ? inputs[((size_t)b * NN + n) * 2 + d] : s[d - 2][b];
        g_x0[row + c] = v;
        g_Xa[row + c] = __float2bfloat16(v);
    }
}

// ---------------- K6: x0 state-columns <- r*states ----------------
__global__ void update_x0_k() {
    int n = blockIdx.x, tid = threadIdx.x;
    __shared__ float s[64][33];
    for (int i = tid; i < BATCH * HID; i += 256) {
        int b = i >> 6, h = i & 63;
        s[h][b] = g_rs[((size_t)b * NN + n) * HID + h];
    }
    __syncthreads();
    size_t row = (size_t)n * CDIM;
    for (int c = 64 + tid; c < CDIM; c += 256) {
        int d = c >> 5, b = c & 31;
        float v = s[d - 2][b];
        g_x0[row + c] = v;
        g_Xa[row + c] = __float2bfloat16(v);
    }
}

// ---------------- GEMM: out = A @ X   (bf16 x bf16 -> fp32) ----------------
// MODE 0: X=g_Xa, write fp32->g_x1 and bf16->g_Xb
// MODE 1: X=g_Xb, write fp32 (2*acc - g_x0) -> g_x2
template <int MODE>
__global__ __launch_bounds__(256) void gemm_kernel() {
    const __nv_bfloat16* __restrict__ A = g_Abf;
    const __nv_bfloat16* __restrict__ X = (MODE == 0) ? g_Xa : g_Xb;

    __shared__ alignas(16) char shraw[36864];
    __nv_bfloat16* As = (__nv_bfloat16*)shraw;             // [2][128][24]
    __nv_bfloat16* Bs = (__nv_bfloat16*)(shraw + 12288);   // [2][16][72]
    float*         Cs = (float*)shraw;                     // [128][72]
#define AS_(s,r,c) As[(s)*3072 + (r)*24 + (c)]
#define BS_(s,r,c) Bs[(s)*1152 + (r)*72 + (c)]

    const int tid  = threadIdx.x;
    const int bm   = blockIdx.y, bn = blockIdx.x;
    const int warp = tid >> 5;
    const int wr   = warp & 3, wc = warp >> 2;   // 4x2 warp grid -> 32x32 per warp

    wmma::fragment<wmma::accumulator, 16, 16, 16, float> acc[2][2];
#pragma unroll
    for (int i = 0; i < 2; ++i)
#pragma unroll
        for (int j = 0; j < 2; ++j) wmma::fill_fragment(acc[i][j], 0.0f);

    // A tile loaders: 256 threads x 16B = 128 rows x 32B
    const int  arow  = tid >> 1, ahalf = tid & 1;
    const int  garow = bm * 128 + arow;
    const bool aval  = garow < NN;
    const __nv_bfloat16* asrc = A + (size_t)(aval ? garow : 0) * NN + ahalf * 8;
    // B tile loaders: 128 threads x 16B = 16 rows x 128B
    const int  brow = tid >> 3, bc8 = tid & 7;
    const __nv_bfloat16* bsrc = X + (size_t)brow * CDIM + (size_t)bn * 64 + bc8 * 8;

    cp16(&AS_(0, arow, ahalf * 8), asrc, aval);
    if (tid < 128) cp16(&BS_(0, brow, bc8 * 8), bsrc, true);
    cp_commit();

    const int KT = NN / 16;   // 625
    for (int k = 0; k < KT; ++k) {
        int s = k & 1;
        if (k + 1 < KT) {
            int ns = s ^ 1;
            cp16(&AS_(ns, arow, ahalf * 8), asrc + (size_t)(k + 1) * 16, aval);
            if (tid < 128) cp16(&BS_(ns, brow, bc8 * 8), bsrc + (size_t)(k + 1) * 16 * CDIM, true);
        }
        cp_commit();
        cp_wait1();
        __syncthreads();

        wmma::fragment<wmma::matrix_a, 16, 16, 16, __nv_bfloat16, wmma::row_major> af;
        wmma::fragment<wmma::matrix_b, 16, 16, 16, __nv_bfloat16, wmma::row_major> bfr[2];
        wmma::load_matrix_sync(bfr[0], &BS_(s, 0, wc * 32     ), 72);
        wmma::load_matrix_sync(bfr[1], &BS_(s, 0, wc * 32 + 16), 72);
#pragma unroll
        for (int i = 0; i < 2; ++i) {
            wmma::load_matrix_sync(af, &AS_(s, wr * 32 + i * 16, 0), 24);
            wmma::mma_sync(acc[i][0], af, bfr[0], acc[i][0]);
            wmma::mma_sync(acc[i][1], af, bfr[1], acc[i][1]);
        }
        __syncthreads();
    }

    // epilogue: stage through smem, then fused math + global stores (padded rows, no guards)
#pragma unroll
    for (int i = 0; i < 2; ++i)
#pragma unroll
        for (int j = 0; j < 2; ++j)
            wmma::store_matrix_sync(&Cs[(wr * 32 + i * 16) * 72 + wc * 32 + j * 16],
                                    acc[i][j], 72, wmma::mem_row_major);
    __syncthreads();

    for (int i = tid; i < 128 * 16; i += 256) {
        int r = i >> 4, c4 = i & 15;
        float4 v = *(float4*)&Cs[r * 72 + c4 * 4];
        size_t off = (size_t)(bm * 128 + r) * CDIM + (size_t)bn * 64 + c4 * 4;
        if (MODE == 0) {
            *(float4*)(g_x1 + off) = v;
            *(__nv_bfloat162*)(g_Xb + off    ) = __floats2bfloat162_rn(v.x, v.y);
            *(__nv_bfloat162*)(g_Xb + off + 2) = __floats2bfloat162_rn(v.z, v.w);
        } else {
            float4 x = *(const float4*)(g_x0 + off);
            v.x = 2.f * v.x - x.x; v.y = 2.f * v.y - x.y;
            v.z = 2.f * v.z - x.z; v.w = 2.f * v.w - x.w;
            *(float4*)(g_x2 + off) = v;
        }
    }
#undef AS_
#undef BS_
}

// ---------------- K5: ru = sigmoid(xk @ Wru + bru); emit u and r*states ----------------
__global__ __launch_bounds__(256) void ru_kernel(const float* __restrict__ Wru,
                                                 const float* __restrict__ bru,
                                                 const float* __restrict__ states) {
    int n = blockIdx.x, tid = threadIdx.x;
    __shared__ float xr[3][CDIM];
    {
        const float4* p0 = (const float4*)(g_x0 + (size_t)n * CDIM);
        const float4* p1 = (const float4*)(g_x1 + (size_t)n * CDIM);
        const float4* p2 = (const float4*)(g_x2 + (size_t)n * CDIM);
        for (int i = tid; i < CDIM / 4; i += 256) {
            ((float4*)xr[0])[i] = p0[i];
            ((float4*)xr[1])[i] = p1[i];
            ((float4*)xr[2])[i] = p2[i];
        }
    }
    __syncthreads();

    const int hq = tid & 31, bg = tid >> 5;   // h0 = hq*4 in [0,128), b = bg + 8j
    const int h0 = hq * 4;
    float4 acc[4];
    float4 bb = *(const float4*)&bru[h0];
#pragma unroll
    for (int j = 0; j < 4; ++j) acc[j] = bb;

    for (int d = 0; d < DFE; ++d) {
        float4 w0 = *(const float4*)&Wru[(d * 3 + 0) * 128 + h0];
        float4 w1 = *(const float4*)&Wru[(d * 3 + 1) * 128 + h0];
        float4 w2 = *(const float4*)&Wru[(d * 3 + 2) * 128 + h0];
#pragma unroll
        for (int j = 0; j < 4; ++j) {
            int b = bg + 8 * j;
            float x0v = xr[0][d * 32 + b];
            float x1v = xr[1][d * 32 + b];
            float x2v = xr[2][d * 32 + b];
            acc[j].x += x0v * w0.x + x1v * w1.x + x2v * w2.x;
            acc[j].y += x0v * w0.y + x1v * w1.y + x2v * w2.y;
            acc[j].z += x0v * w0.z + x1v * w1.z + x2v * w2.z;
            acc[j].w += x0v * w0.w + x1v * w1.w + x2v * w2.w;
        }
    }

#pragma unroll
    for (int j = 0; j < 4; ++j) {
        int b = bg + 8 * j;
        size_t base = ((size_t)b * NN + n) * HID;
        float4 s4;
        s4.x = sigf(acc[j].x); s4.y = sigf(acc[j].y);
        s4.z = sigf(acc[j].z); s4.w = sigf(acc[j].w);
        if (h0 < 64) {  // r half
            float4 sv = *(const float4*)&states[base + h0];
            float4 rs;
            rs.x = s4.x * sv.x; rs.y = s4.y * sv.y;
            rs.z = s4.z * sv.z; rs.w = s4.w * sv.w;
            *(float4*)&g_rs[base + h0] = rs;
        } else {        // u half
            *(float4*)&g_u[base + h0 - 64] = s4;
        }
    }
}

// ---------------- K9: c = tanh(xk @ Wc + bc); out = u*s + (1-u)*c ----------------
__global__ __launch_bounds__(256) void out_kernel(const float* __restrict__ Wc,
                                                  const float* __restrict__ bc,
                                                  const float* __restrict__ states,
                                                  float* __restrict__ out) {
    int n = blockIdx.x, tid = threadIdx.x;
    __shared__ float xr[3][CDIM];
    {
        const float4* p0 = (const float4*)(g_x0 + (size_t)n * CDIM);
        const float4* p1 = (const float4*)(g_x1 + (size_t)n * CDIM);
        const float4* p2 = (const float4*)(g_x2 + (size_t)n * CDIM);
        for (int i = tid; i < CDIM / 4; i += 256) {
            ((float4*)xr[0])[i] = p0[i];
            ((float4*)xr[1])[i] = p1[i];
            ((float4*)xr[2])[i] = p2[i];
        }
    }
    __syncthreads();

    const int hq = tid & 15, bg = tid >> 4;   // h0 = hq*4 in [0,64), b = bg + 16j
    const int h0 = hq * 4;
    float4 acc[2];
    float4 bb = *(const float4*)&bc[h0];
    acc[0] = bb; acc[1] = bb;

    for (int d = 0; d < DFE; ++d) {
        float4 w0 = *(const float4*)&Wc[(d * 3 + 0) * 64 + h0];
        float4 w1 = *(const float4*)&Wc[(d * 3 + 1) * 64 + h0];
        float4 w2 = *(const float4*)&Wc[(d * 3 + 2) * 64 + h0];
#pragma unroll
        for (int j = 0; j < 2; ++j) {
            int b = bg + 16 * j;
            float x0v = xr[0][d * 32 + b];
            float x1v = xr[1][d * 32 + b];
            float x2v = xr[2][d * 32 + b];
            acc[j].x += x0v * w0.x + x1v * w1.x + x2v * w2.x;
            acc[j].y += x0v * w0.y + x1v * w1.y + x2v * w2.y;
            acc[j].z += x0v * w0.z + x1v * w1.z + x2v * w2.z;
            acc[j].w += x0v * w0.w + x1v * w1.w + x2v * w2.w;
        }
    }

#pragma unroll
    for (int j = 0; j < 2; ++j) {
        int b = bg + 16 * j;
        size_t base = ((size_t)b * NN + n) * HID + h0;
        float4 u4 = *(const float4*)&g_u[base];
        float4 sv = *(const float4*)&states[base];
        float4 o;
        float c0 = tanhf(acc[j].x), c1 = tanhf(acc[j].y),
              c2 = tanhf(acc[j].z), c3 = tanhf(acc[j].w);
        o.x = u4.x * sv.x + (1.f - u4.x) * c0;
        o.y = u4.y * sv.y + (1.f - u4.y) * c1;
        o.z = u4.z * sv.z + (1.f - u4.z) * c2;
        o.w = u4.w * sv.w + (1.f - u4.w) * c3;
        *(float4*)&out[base] = o;
    }
}

// ---------------- launcher ----------------
extern "C" void kernel_launch(void* const* d_in, const int* in_sizes, int n_in,
                              void* d_out, int out_size) {
    const float *inputs = nullptr, *states = nullptr, *A = nullptr;
    const float *Wru = nullptr, *bru = nullptr, *Wc = nullptr, *bc = nullptr;
    for (int i = 0; i < n_in; ++i) {
        const float* p = (const float*)d_in[i];
        switch (in_sizes[i]) {
            case 640000:    inputs = p; break;
            case 20480000:  states = p; break;
            case 100000000: A      = p; break;
            case 25344:     Wru    = p; break;
            case 128:       bru    = p; break;
            case 12672:     Wc     = p; break;
            case 64:        bc     = p; break;
            default: break;
        }
    }
    float* out = (float*)d_out;

    conv_A<<<2048, 256>>>(A);
    build_x0_k<<<NN, 256>>>(inputs, states);

    dim3 g(CDIM / 64, NPAD / 128);   // 33 x 79
    gemm_kernel<0><<<g, 256>>>();    // x1 = A @ x0
    gemm_kernel<1><<<g, 256>>>();    // x2 = 2*A@x1 - x0
    ru_kernel<<<NN, 256>>>(Wru, bru, states);
    update_x0_k<<<NN, 256>>>();
    gemm_kernel<0><<<g, 256>>>();    // x1' = A @ x0'
    gemm_kernel<1><<<g, 256>>>();    // x2' = 2*A@x1' - x0'
    out_kernel<<<NN, 256>>>(Wc, bc, states, out);
}

// round 10
// speedup vs baseline: 2.8745x; 1.8720x over previous
#include <cuda_runtime.h>
#include <cuda_bf16.h>
#include <cstdint>
#include <cstddef>

#define NN    10000
#define KP    10048          // 157 * 64  (K padded, A col dim)
#define MPAD  10112          // 79 * 128  (M padded)
#define CPAD  2304           // 9 * 256   (feature dim padded)
#define CDIM  2112           // 66 * 32
#define KT_   157
#define BATCH 32
#define HID   64
#define DFE   66
#define STAGE_BYTES 49152    // A 16KB + B 32KB

// ---------------- scratch (__device__ globals; zero-initialized; pads never written) ----------------
__device__ __nv_bfloat16 g_Abf[(size_t)MPAD * KP];    // A bf16 [m][k]
__device__ __nv_bfloat16 g_Xa [(size_t)KP * CPAD];    // X bf16 [k][c]   (gconv input)
__device__ __nv_bfloat16 g_Xb [(size_t)KP * CPAD];    // A@X bf16 [k][c]
__device__ float g_x0[(size_t)NN * CDIM];
__device__ float g_x1[(size_t)NN * CDIM];
__device__ float g_x2[(size_t)NN * CDIM];
__device__ float g_u [(size_t)BATCH * NN * HID];
__device__ float g_rs[(size_t)BATCH * NN * HID];

// ---------------- helpers ----------------
__device__ __forceinline__ uint32_t s2u(const void* p) {
    uint32_t a;
    asm("{ .reg .u64 t; cvta.to.shared.u64 t, %1; cvt.u32.u64 %0, t; }" : "=r"(a) : "l"(p));
    return a;
}
__device__ __forceinline__ void cp16(uint32_t dst, const void* src) {
    asm volatile("cp.async.cg.shared.global [%0], [%1], 16;\n" :: "r"(dst), "l"(src));
}
__device__ __forceinline__ void cp_commit() { asm volatile("cp.async.commit_group;\n"); }
template <int N>
__device__ __forceinline__ void cp_wait() { asm volatile("cp.async.wait_group %0;\n" :: "n"(N)); }

__device__ __forceinline__ void ldsm4(uint32_t* r, uint32_t addr) {
    asm volatile("ldmatrix.sync.aligned.m8n8.x4.shared.b16 {%0,%1,%2,%3}, [%4];"
                 : "=r"(r[0]), "=r"(r[1]), "=r"(r[2]), "=r"(r[3]) : "r"(addr));
}
__device__ __forceinline__ void ldsm4t(uint32_t& r0, uint32_t& r1, uint32_t& r2, uint32_t& r3,
                                       uint32_t addr) {
    asm volatile("ldmatrix.sync.aligned.m8n8.x4.trans.shared.b16 {%0,%1,%2,%3}, [%4];"
                 : "=r"(r0), "=r"(r1), "=r"(r2), "=r"(r3) : "r"(addr));
}
__device__ __forceinline__ void mma16816(float* c, const uint32_t* a, const uint32_t* b) {
    asm volatile("mma.sync.aligned.m16n8k16.row.col.f32.bf16.bf16.f32 "
                 "{%0,%1,%2,%3}, {%4,%5,%6,%7}, {%8,%9}, {%0,%1,%2,%3};"
                 : "+f"(c[0]), "+f"(c[1]), "+f"(c[2]), "+f"(c[3])
                 : "r"(a[0]), "r"(a[1]), "r"(a[2]), "r"(a[3]), "r"(b[0]), "r"(b[1]));
}
__device__ __forceinline__ float sigf(float x) { return 1.f / (1.f + __expf(-x)); }

// ---------------- K1: A fp32 -> bf16 (stride KP; pads stay zero) ----------------
__global__ void conv_A(const float* __restrict__ A) {
    int m = blockIdx.y;
    int x4 = blockIdx.x * blockDim.x + threadIdx.x;   // 0..2559
    if (x4 >= NN / 4) return;
    float4 f = ((const float4*)(A + (size_t)m * NN))[x4];
    __nv_bfloat162* dst = (__nv_bfloat162*)(g_Abf + (size_t)m * KP + x4 * 4);
    dst[0] = __floats2bfloat162_rn(f.x, f.y);
    dst[1] = __floats2bfloat162_rn(f.z, f.w);
}

// ---------------- build g_x0 fp32 [n][c] and g_Xa bf16 [n][c] ----------------
__global__ void build_x0_k(const float* __restrict__ inputs, const float* __restrict__ states) {
    int n = blockIdx.x, tid = threadIdx.x;
    __shared__ float s[64][33];
    for (int i = tid; i < BATCH * HID; i += 256) {
        int b = i >> 6, h = i & 63;
        s[h][b] = states[((size_t)b * NN + n) * HID + h];
    }
    __syncthreads();
    size_t r0 = (size_t)n * CDIM, r1 = (size_t)n * CPAD;
    for (int c = tid; c < CDIM; c += 256) {
        int d = c >> 5, b = c & 31;
        float v = (d < 2) ? inputs[((size_t)b * NN + n) * 2 + d] : s[d - 2][b];
        g_x0[r0 + c] = v;
        g_Xa[r1 + c] = __float2bfloat16(v);
    }
}

// ---------------- update state cols of g_x0/g_Xa from g_rs ----------------
__global__ void update_x0_k() {
    int n = blockIdx.x, tid = threadIdx.x;
    __shared__ float s[64][33];
    for (int i = tid; i < BATCH * HID; i += 256) {
        int b = i >> 6, h = i & 63;
        s[h][b] = g_rs[((size_t)b * NN + n) * HID + h];
    }
    __syncthreads();
    size_t r0 = (size_t)n * CDIM, r1 = (size_t)n * CPAD;
    for (int c = 64 + tid; c < CDIM; c += 256) {
        int d = c >> 5, b = c & 31;
        float v = s[d - 2][b];
        g_x0[r0 + c] = v;
        g_Xa[r1 + c] = __float2bfloat16(v);
    }
}

// ---------------- mma.sync GEMM: D[128 x 256] tile of A @ X ----------------
// MODE 0: X = g_Xa; writes fp32 -> g_x1 and bf16 -> g_Xb
// MODE 1: X = g_Xb; writes (2*acc - g_x0) -> g_x2
template <int MODE>
__global__ __launch_bounds__(256, 1) void gemm_mma() {
    extern __shared__ char dyn[];
    const __nv_bfloat16* __restrict__ Xsrc = (MODE == 0) ? g_Xa : g_Xb;

    const int tid = threadIdx.x;
    const int wid = tid >> 5, lid = tid & 31;
    const int wm = wid >> 2, wn = wid & 3;        // 2 x 4 warp grid, 64x64 warp tiles
    const int m0 = blockIdx.y * 128;
    const int c0 = blockIdx.x * 256;
    const uint32_t sbase = s2u(dyn);

    float acc[4][8][4];
#pragma unroll
    for (int i = 0; i < 4; ++i)
#pragma unroll
        for (int j = 0; j < 8; ++j)
#pragma unroll
            for (int q = 0; q < 4; ++q) acc[i][j][q] = 0.f;

    auto load_stage = [&](int s, int kt) {
        const uint32_t As = sbase + s * STAGE_BYTES;
        const uint32_t Bs = As + 16384;
        const __nv_bfloat16* ap = g_Abf + (size_t)m0 * KP + kt * 64;
        const __nv_bfloat16* bp = Xsrc + (size_t)(kt * 64) * CPAD + c0;
        // A: 128 rows x 8 chunks (16B) = 1024
#pragma unroll
        for (int i = 0; i < 4; ++i) {
            int id = tid + 256 * i;
            int r = id >> 3, c = id & 7;
            cp16(As + r * 128 + (((c ^ (r & 7)) << 4)), ap + (size_t)r * KP + c * 8);
        }
        // B: 64 rows x 32 chunks (16B) = 2048
#pragma unroll
        for (int i = 0; i < 8; ++i) {
            int id = tid + 256 * i;
            int r = id >> 5, c = id & 31;
            cp16(Bs + r * 512 + (((c ^ (r & 7)) << 4)), bp + (size_t)r * CPAD + c * 8);
        }
        cp_commit();
    };

    const int lrow = lid & 15, lchk = lid >> 4;
    const int xr = lrow & 7;

    auto compute = [&](int s) {
        const uint32_t sA = sbase + s * STAGE_BYTES;
        const uint32_t sB = sA + 16384;
#pragma unroll
        for (int kk = 0; kk < 4; ++kk) {
            uint32_t af[4][4];
#pragma unroll
            for (int i = 0; i < 4; ++i) {
                int r = wm * 64 + i * 16 + lrow;
                int c = kk * 2 + lchk;
                ldsm4(af[i], sA + r * 128 + (((c ^ xr) << 4)));
            }
            uint32_t bf[8][2];
#pragma unroll
            for (int p = 0; p < 4; ++p) {
                int r = kk * 16 + lrow;
                int c = wn * 8 + p * 2 + lchk;
                ldsm4t(bf[2*p][0], bf[2*p][1], bf[2*p+1][0], bf[2*p+1][1],
                       sB + r * 512 + (((c ^ xr) << 4)));
            }
#pragma unroll
            for (int i = 0; i < 4; ++i)
#pragma unroll
                for (int j = 0; j < 8; ++j)
                    mma16816(acc[i][j], af[i], bf[j]);
        }
    };

    // prologue: stages 0,1
    load_stage(0, 0);
    load_stage(1, 1);

    for (int kt = 0; kt < KT_; ++kt) {
        cp_wait<1>();
        __syncthreads();
        if (kt + 2 < KT_) load_stage((kt + 2) % 3, kt + 2);
        cp_commit();
        compute(kt % 3);
    }

    // ---------------- fused epilogue ----------------
    const int q = lid >> 2, t4 = lid & 3;
#pragma unroll
    for (int i = 0; i < 4; ++i) {
        const int ra = m0 + wm * 64 + i * 16 + q;   // row for c0,c1
        const int rb = ra + 8;                      // row for c2,c3
#pragma unroll
        for (int j = 0; j < 8; ++j) {
            const int cc = c0 + wn * 64 + j * 8 + t4 * 2;
            if (cc >= CDIM) continue;
            const float* a = acc[i][j];
            if (MODE == 0) {
                if (ra < NN) {
                    *(float2*)(g_x1 + (size_t)ra * CDIM + cc) = make_float2(a[0], a[1]);
                    *(__nv_bfloat162*)(g_Xb + (size_t)ra * CPAD + cc) =
                        __floats2bfloat162_rn(a[0], a[1]);
                }
                if (rb < NN) {
                    *(float2*)(g_x1 + (size_t)rb * CDIM + cc) = make_float2(a[2], a[3]);
                    *(__nv_bfloat162*)(g_Xb + (size_t)rb * CPAD + cc) =
                        __floats2bfloat162_rn(a[2], a[3]);
                }
            } else {
                if (ra < NN) {
                    float2 x = *(const float2*)(g_x0 + (size_t)ra * CDIM + cc);
                    *(float2*)(g_x2 + (size_t)ra * CDIM + cc) =
                        make_float2(2.f * a[0] - x.x, 2.f * a[1] - x.y);
                }
                if (rb < NN) {
                    float2 x = *(const float2*)(g_x0 + (size_t)rb * CDIM + cc);
                    *(float2*)(g_x2 + (size_t)rb * CDIM + cc) =
                        make_float2(2.f * a[2] - x.x, 2.f * a[3] - x.y);
                }
            }
        }
    }
}

// ---------------- ru = sigmoid(xk @ Wru + bru); emit u and r*states ----------------
__global__ __launch_bounds__(256) void ru_kernel(const float* __restrict__ Wru,
                                                 const float* __restrict__ bru,
                                                 const float* __restrict__ states) {
    int n = blockIdx.x, tid = threadIdx.x;
    __shared__ float xr[3][CDIM];
    {
        const float4* p0 = (const float4*)(g_x0 + (size_t)n * CDIM);
        const float4* p1 = (const float4*)(g_x1 + (size_t)n * CDIM);
        const float4* p2 = (const float4*)(g_x2 + (size_t)n * CDIM);
        for (int i = tid; i < CDIM / 4; i += 256) {
            ((float4*)xr[0])[i] = p0[i];
            ((float4*)xr[1])[i] = p1[i];
            ((float4*)xr[2])[i] = p2[i];
        }
    }
    __syncthreads();

    const int hq = tid & 31, bg = tid >> 5;
    const int h0 = hq * 4;
    float4 acc[4];
    float4 bb = *(const float4*)&bru[h0];
#pragma unroll
    for (int j = 0; j < 4; ++j) acc[j] = bb;

    for (int d = 0; d < DFE; ++d) {
        float4 w0 = *(const float4*)&Wru[(d * 3 + 0) * 128 + h0];
        float4 w1 = *(const float4*)&Wru[(d * 3 + 1) * 128 + h0];
        float4 w2 = *(const float4*)&Wru[(d * 3 + 2) * 128 + h0];
#pragma unroll
        for (int j = 0; j < 4; ++j) {
            int b = bg + 8 * j;
            float x0v = xr[0][d * 32 + b];
            float x1v = xr[1][d * 32 + b];
            float x2v = xr[2][d * 32 + b];
            acc[j].x += x0v * w0.x + x1v * w1.x + x2v * w2.x;
            acc[j].y += x0v * w0.y + x1v * w1.y + x2v * w2.y;
            acc[j].z += x0v * w0.z + x1v * w1.z + x2v * w2.z;
            acc[j].w += x0v * w0.w + x1v * w1.w + x2v * w2.w;
        }
    }

#pragma unroll
    for (int j = 0; j < 4; ++j) {
        int b = bg + 8 * j;
        size_t base = ((size_t)b * NN + n) * HID;
        float4 s4;
        s4.x = sigf(acc[j].x); s4.y = sigf(acc[j].y);
        s4.z = sigf(acc[j].z); s4.w = sigf(acc[j].w);
        if (h0 < 64) {
            float4 sv = *(const float4*)&states[base + h0];
            float4 rs;
            rs.x = s4.x * sv.x; rs.y = s4.y * sv.y;
            rs.z = s4.z * sv.z; rs.w = s4.w * sv.w;
            *(float4*)&g_rs[base + h0] = rs;
        } else {
            *(float4*)&g_u[base + h0 - 64] = s4;
        }
    }
}

// ---------------- c = tanh(xk @ Wc + bc); out = u*s + (1-u)*c ----------------
__global__ __launch_bounds__(256) void out_kernel(const float* __restrict__ Wc,
                                                  const float* __restrict__ bc,
                                                  const float* __restrict__ states,
                                                  float* __restrict__ out) {
    int n = blockIdx.x, tid = threadIdx.x;
    __shared__ float xr[3][CDIM];
    {
        const float4* p0 = (const float4*)(g_x0 + (size_t)n * CDIM);
        const float4* p1 = (const float4*)(g_x1 + (size_t)n * CDIM);
        const float4* p2 = (const float4*)(g_x2 + (size_t)n * CDIM);
        for (int i = tid; i < CDIM / 4; i += 256) {
            ((float4*)xr[0])[i] = p0[i];
            ((float4*)xr[1])[i] = p1[i];
            ((float4*)xr[2])[i] = p2[i];
        }
    }
    __syncthreads();

    const int hq = tid & 15, bg = tid >> 4;
    const int h0 = hq * 4;
    float4 acc[2];
    float4 bb = *(const float4*)&bc[h0];
    acc[0] = bb; acc[1] = bb;

    for (int d = 0; d < DFE; ++d) {
        float4 w0 = *(const float4*)&Wc[(d * 3 + 0) * 64 + h0];
        float4 w1 = *(const float4*)&Wc[(d * 3 + 1) * 64 + h0];
        float4 w2 = *(const float4*)&Wc[(d * 3 + 2) * 64 + h0];
#pragma unroll
        for (int j = 0; j < 2; ++j) {
            int b = bg + 16 * j;
            float x0v = xr[0][d * 32 + b];
            float x1v = xr[1][d * 32 + b];
            float x2v = xr[2][d * 32 + b];
            acc[j].x += x0v * w0.x + x1v * w1.x + x2v * w2.x;
            acc[j].y += x0v * w0.y + x1v * w1.y + x2v * w2.y;
            acc[j].z += x0v * w0.z + x1v * w1.z + x2v * w2.z;
            acc[j].w += x0v * w0.w + x1v * w1.w + x2v * w2.w;
        }
    }

#pragma unroll
    for (int j = 0; j < 2; ++j) {
        int b = bg + 16 * j;
        size_t base = ((size_t)b * NN + n) * HID + h0;
        float4 u4 = *(const float4*)&g_u[base];
        float4 sv = *(const float4*)&states[base];
        float4 o;
        float c0 = tanhf(acc[j].x), c1 = tanhf(acc[j].y),
              c2 = tanhf(acc[j].z), c3 = tanhf(acc[j].w);
        o.x = u4.x * sv.x + (1.f - u4.x) * c0;
        o.y = u4.y * sv.y + (1.f - u4.y) * c1;
        o.z = u4.z * sv.z + (1.f - u4.z) * c2;
        o.w = u4.w * sv.w + (1.f - u4.w) * c3;
        *(float4*)&out[base] = o;
    }
}

// ---------------- launcher ----------------
extern "C" void kernel_launch(void* const* d_in, const int* in_sizes, int n_in,
                              void* d_out, int out_size) {
    const float *inputs = nullptr, *states = nullptr, *A = nullptr;
    const float *Wru = nullptr, *bru = nullptr, *Wc = nullptr, *bc = nullptr;
    for (int i = 0; i < n_in; ++i) {
        const float* p = (const float*)d_in[i];
        switch (in_sizes[i]) {
            case 640000:    inputs = p; break;
            case 20480000:  states = p; break;
            case 100000000: A      = p; break;
            case 25344:     Wru    = p; break;
            case 128:       bru    = p; break;
            case 12672:     Wc     = p; break;
            case 64:        bc     = p; break;
            default: break;
        }
    }
    float* out = (float*)d_out;

    const int SMEMSZ = 3 * STAGE_BYTES;   // 147456
    cudaFuncSetAttribute(gemm_mma<0>, cudaFuncAttributeMaxDynamicSharedMemorySize, SMEMSZ);
    cudaFuncSetAttribute(gemm_mma<1>, cudaFuncAttributeMaxDynamicSharedMemorySize, SMEMSZ);

    conv_A<<<dim3(10, NN), 256>>>(A);
    build_x0_k<<<NN, 256>>>(inputs, states);

    dim3 g(CPAD / 256, MPAD / 128);       // 9 x 79
    gemm_mma<0><<<g, 256, SMEMSZ>>>();    // x1 = A @ x0   (+ bf16 copy)
    gemm_mma<1><<<g, 256, SMEMSZ>>>();    // x2 = 2*A@x1 - x0
    ru_kernel<<<NN, 256>>>(Wru, bru, states);
    update_x0_k<<<NN, 256>>>();
    gemm_mma<0><<<g, 256, SMEMSZ>>>();    // x1' (+ bf16 copy)
    gemm_mma<1><<<g, 256, SMEMSZ>>>();    // x2'
    out_kernel<<<NN, 256>>>(Wc, bc, states, out);
}